// round 1
// baseline (speedup 1.0000x reference)
#include <cuda_runtime.h>
#include <math.h>

// Shapes (fixed by the problem)
#define BB 8
#define TT 512
#define DD 128
#define HH 8

// Scratch (allocation-free rule: __device__ globals)
__device__ float g_q[BB*HH*TT*DD];   // q[b][h][t][d]
__device__ float g_v[BB*HH*TT*DD];   // v[b][h][s][d]
__device__ float g_o[BB*HH*TT*DD];   // per-head attention output o[b][h][t][d]

// ---------------------------------------------------------------------------
// Kernel 1: QV projection.  y[bt][o] = sum_k x[bt][k] * Wqv[o][k] + Wqv[o][128]
// o = h*256 + c ;  c<128 -> q[b][h][t][c] ; c>=128 -> v[b][h][t][c-128]
// Tile: 64 (bt) x 64 (o), 256 threads, 4x4 micro (cols strided by 16).
// ---------------------------------------------------------------------------
__global__ __launch_bounds__(256) void qv_kernel(const float* __restrict__ x,
                                                 const float* __restrict__ w) {
    extern __shared__ float sm[];
    float* xs = sm;              // 64*128 (reads are quarter-warp broadcast -> no pad)
    float* ws = sm + 64*128;     // 64*132 (padded)
    __shared__ float bsh[64];

    const int tid = threadIdx.x;
    const int tx  = tid & 15, ty = tid >> 4;
    const int m0 = blockIdx.y * 64;   // bt tile
    const int n0 = blockIdx.x * 64;   // o tile

    // stage x tile (contiguous copy, float4)
    const float4* xg = (const float4*)(x + m0*DD);
    for (int i = tid; i < 64*32; i += 256)
        ((float4*)xs)[i] = xg[i];
    // stage W tile (row length 129 in gmem)
    for (int i = tid; i < 64*128; i += 256) {
        int r = i >> 7, c = i & 127;
        ws[r*132 + c] = w[(size_t)(n0 + r)*129 + c];
    }
    if (tid < 64) bsh[tid] = w[(size_t)(n0 + tid)*129 + 128];
    __syncthreads();

    float acc[4][4];
#pragma unroll
    for (int i = 0; i < 4; i++)
#pragma unroll
        for (int j = 0; j < 4; j++) acc[i][j] = 0.f;

#pragma unroll 4
    for (int k = 0; k < 128; k += 4) {
        float4 a[4], b[4];
#pragma unroll
        for (int i = 0; i < 4; i++) a[i] = *(const float4*)&xs[(ty*4 + i)*128 + k];
#pragma unroll
        for (int j = 0; j < 4; j++) b[j] = *(const float4*)&ws[(tx + 16*j)*132 + k];
#pragma unroll
        for (int i = 0; i < 4; i++)
#pragma unroll
            for (int j = 0; j < 4; j++) {
                acc[i][j] += a[i].x*b[j].x + a[i].y*b[j].y + a[i].z*b[j].z + a[i].w*b[j].w;
            }
    }

#pragma unroll
    for (int i = 0; i < 4; i++) {
        int m  = m0 + ty*4 + i;           // bt index
        int bi = m >> 9, t = m & 511;
#pragma unroll
        for (int j = 0; j < 4; j++) {
            int o  = n0 + tx + 16*j;
            int hh = o >> 8, c = o & 255;
            float val = acc[i][j] + bsh[tx + 16*j];
            float* dst = (c < 128) ? g_q : g_v;
            dst[(((size_t)(bi*HH + hh))*TT + t)*DD + (c & 127)] = val;
        }
    }
}

// ---------------------------------------------------------------------------
// Kernel 2: fused L1-distance attention per (b, h, 64 t-rows).
// S[r][s] = -(1/sqrt(128)) * sum_d |q[r][d] - x[s][d]*wk[h][d]|
// softmax over s, * msk, then O[r][d] = sum_s P[r][s] * v[s][d]
// ---------------------------------------------------------------------------
__global__ __launch_bounds__(256) void attn_kernel(const float* __restrict__ x,
                                                   const float* __restrict__ wk,
                                                   const float* __restrict__ msk) {
    extern __shared__ float sm[];
    float* Ssh = sm;                 // 64*512
    float* qsh = sm + 64*512;        // 64*132
    float* ksh = qsh + 64*132;       // 64*132
    __shared__ float wksh[128];

    const int b  = blockIdx.z, h = blockIdx.y;
    const int t0 = blockIdx.x * 64;
    const int tid = threadIdx.x;
    const int tx  = tid & 15, ty = tid >> 4;

    if (tid < 128) wksh[tid] = wk[h*DD + tid];

    // stage q tile
    const float4* qg = (const float4*)(g_q + (((size_t)(b*HH + h))*TT + t0)*DD);
    for (int i = tid; i < 64*32; i += 256) {
        int r = i >> 5, c4 = i & 31;
        float4 v = qg[i];
        *(float4*)&qsh[r*132 + c4*4] = v;
    }
    __syncthreads();

    const float NEG_ISQ = -0.08838834764831845f;  // -1/sqrt(128)

    // Phase 1: all score tiles
    for (int s0 = 0; s0 < TT; s0 += 64) {
        const float4* xg = (const float4*)(x + ((size_t)b*TT + s0)*DD);
        for (int i = tid; i < 64*32; i += 256) {
            int r = i >> 5, c4 = i & 31;
            float4 v = xg[i];
            v.x *= wksh[c4*4 + 0]; v.y *= wksh[c4*4 + 1];
            v.z *= wksh[c4*4 + 2]; v.w *= wksh[c4*4 + 3];
            *(float4*)&ksh[r*132 + c4*4] = v;
        }
        __syncthreads();

        float acc[4][4];
#pragma unroll
        for (int i = 0; i < 4; i++)
#pragma unroll
            for (int j = 0; j < 4; j++) acc[i][j] = 0.f;

#pragma unroll 4
        for (int d = 0; d < 128; d += 4) {
            float4 qv[4], kv[4];
#pragma unroll
            for (int i = 0; i < 4; i++) qv[i] = *(const float4*)&qsh[(ty*4 + i)*132 + d];
#pragma unroll
            for (int j = 0; j < 4; j++) kv[j] = *(const float4*)&ksh[(tx + 16*j)*132 + d];
#pragma unroll
            for (int i = 0; i < 4; i++)
#pragma unroll
                for (int j = 0; j < 4; j++) {
                    acc[i][j] += fabsf(qv[i].x - kv[j].x) + fabsf(qv[i].y - kv[j].y)
                               + fabsf(qv[i].z - kv[j].z) + fabsf(qv[i].w - kv[j].w);
                }
        }
#pragma unroll
        for (int i = 0; i < 4; i++)
#pragma unroll
            for (int j = 0; j < 4; j++)
                Ssh[(ty*4 + i)*512 + s0 + tx + 16*j] = acc[i][j] * NEG_ISQ;
        __syncthreads();
    }

    // Phase 2: row softmax + mask  (8 warps, 8 rows each)
    const int warp = tid >> 5, lane = tid & 31;
    for (int r = warp; r < 64; r += 8) {
        float* row = Ssh + r*512;
        float vals[16];
        float m = -1e30f;
#pragma unroll
        for (int i = 0; i < 16; i++) { vals[i] = row[lane + i*32]; m = fmaxf(m, vals[i]); }
#pragma unroll
        for (int o = 16; o > 0; o >>= 1) m = fmaxf(m, __shfl_xor_sync(0xffffffffu, m, o));
        float sum = 0.f;
#pragma unroll
        for (int i = 0; i < 16; i++) { vals[i] = __expf(vals[i] - m); sum += vals[i]; }
#pragma unroll
        for (int o = 16; o > 0; o >>= 1) sum += __shfl_xor_sync(0xffffffffu, sum, o);
        float inv = 1.f / sum;
        const float* mrow = msk + ((size_t)(h*TT + t0 + r))*TT;
#pragma unroll
        for (int i = 0; i < 16; i++)
            row[lane + i*32] = vals[i] * inv * mrow[lane + i*32];
    }
    __syncthreads();

    // Phase 3: O = P @ V   (reuse qsh as v tile buffer)
    float* vsh = qsh;
    float oacc[4][8];
#pragma unroll
    for (int i = 0; i < 4; i++)
#pragma unroll
        for (int j = 0; j < 8; j++) oacc[i][j] = 0.f;

    for (int s0 = 0; s0 < TT; s0 += 64) {
        const float4* vg = (const float4*)(g_v + (((size_t)(b*HH + h))*TT + s0)*DD);
        for (int i = tid; i < 64*32; i += 256) {
            int r = i >> 5, c4 = i & 31;
            float4 v = vg[i];
            *(float4*)&vsh[r*132 + c4*4] = v;
        }
        __syncthreads();

#pragma unroll 4
        for (int s = 0; s < 64; s++) {
            float p[4];
#pragma unroll
            for (int i = 0; i < 4; i++) p[i] = Ssh[(ty*4 + i)*512 + s0 + s];
            float4 v0 = *(const float4*)&vsh[s*132 + tx*4];
            float4 v1 = *(const float4*)&vsh[s*132 + 64 + tx*4];
#pragma unroll
            for (int i = 0; i < 4; i++) {
                oacc[i][0] += p[i]*v0.x; oacc[i][1] += p[i]*v0.y;
                oacc[i][2] += p[i]*v0.z; oacc[i][3] += p[i]*v0.w;
                oacc[i][4] += p[i]*v1.x; oacc[i][5] += p[i]*v1.y;
                oacc[i][6] += p[i]*v1.z; oacc[i][7] += p[i]*v1.w;
            }
        }
        __syncthreads();
    }

    float* og = g_o + (((size_t)(b*HH + h))*TT + t0)*DD;
#pragma unroll
    for (int i = 0; i < 4; i++) {
        int r = ty*4 + i;
        float4 w0 = make_float4(oacc[i][0], oacc[i][1], oacc[i][2], oacc[i][3]);
        float4 w1 = make_float4(oacc[i][4], oacc[i][5], oacc[i][6], oacc[i][7]);
        *(float4*)&og[r*DD + tx*4]      = w0;
        *(float4*)&og[r*DD + 64 + tx*4] = w1;
    }
}

// ---------------------------------------------------------------------------
// Kernel 3: bo = sum_h o[b][h][t][:] ; yo = qgelu(bo+4.5)-4.5 ;
//           out = x + yo @ fanout^T + bias
// Block: (b, 16 t-rows), 256 threads.
// ---------------------------------------------------------------------------
__global__ __launch_bounds__(256) void final_kernel(const float* __restrict__ x,
                                                    const float* __restrict__ fw,
                                                    float* __restrict__ out) {
    extern __shared__ float sm[];
    float* Wsh  = sm;            // 128*129 = 16512 floats (same layout as gmem)
    float* yosh = sm + 16512;    // 16*128

    const int b = blockIdx.y, t0 = blockIdx.x * 16;
    const int tid = threadIdx.x;

    for (int i = tid; i < 128*129; i += 256) Wsh[i] = fw[i];

    for (int i = tid; i < 16*128; i += 256) {
        int r = i >> 7, dd = i & 127;
        float bo = 0.f;
#pragma unroll
        for (int h = 0; h < HH; h++)
            bo += g_o[(((size_t)(b*HH + h))*TT + t0 + r)*DD + dd];
        float z  = bo + 4.5f;
        float sg = 1.f / (1.f + __expf(-1.702f * z));
        yosh[r*128 + dd] = z*sg - 4.5f;
    }
    __syncthreads();

    const int o = tid & 127, half = tid >> 7;
    float acc[8];
#pragma unroll
    for (int rr = 0; rr < 8; rr++) acc[rr] = 0.f;

#pragma unroll 4
    for (int i = 0; i < 128; i++) {
        float w = Wsh[o*129 + i];
#pragma unroll
        for (int rr = 0; rr < 8; rr++)
            acc[rr] += w * yosh[(half*8 + rr)*128 + i];
    }
    float bias = Wsh[o*129 + 128];
#pragma unroll
    for (int rr = 0; rr < 8; rr++) {
        int t = t0 + half*8 + rr;
        size_t idx = ((size_t)b*TT + t)*DD + o;
        out[idx] = x[idx] + acc[rr] + bias;
    }
}

// ---------------------------------------------------------------------------
extern "C" void kernel_launch(void* const* d_in, const int* in_sizes, int n_in,
                              void* d_out, int out_size) {
    const float* x   = (const float*)d_in[0];
    const float* msk = (const float*)d_in[1];
    const float* wqv = (const float*)d_in[2];
    const float* wk  = (const float*)d_in[3];
    const float* fw  = (const float*)d_in[4];
    float* out = (float*)d_out;

    cudaFuncSetAttribute(qv_kernel,    cudaFuncAttributeMaxDynamicSharedMemorySize,
                         (64*128 + 64*132) * 4);
    cudaFuncSetAttribute(attn_kernel,  cudaFuncAttributeMaxDynamicSharedMemorySize,
                         (64*512 + 2*64*132) * 4);
    cudaFuncSetAttribute(final_kernel, cudaFuncAttributeMaxDynamicSharedMemorySize,
                         (128*129 + 16*128) * 4);

    // 1) QV projection: grid (N/64, M/64) = (2048/64, 4096/64)
    qv_kernel<<<dim3(32, 64), 256, (64*128 + 64*132) * 4>>>(x, wqv);

    // 2) fused attention: (t-tiles, h, b)
    attn_kernel<<<dim3(TT/64, HH, BB), 256, (64*512 + 2*64*132) * 4>>>(x, wk, msk);

    // 3) head-reduce + gelu + fanout + residual
    final_kernel<<<dim3(TT/16, BB), 256, (128*129 + 16*128) * 4>>>(x, fw, out);
}